// round 2
// baseline (speedup 1.0000x reference)
#include <cuda_runtime.h>

#define BATCH_N 262144
#define NBLK    1024
#define TPB     256

__device__ float g_partials[NBLK];
__device__ unsigned int g_count = 0;

// ---- packed f32x2 helpers (sm_103a) ----
__device__ __forceinline__ unsigned long long pk2(float lo, float hi) {
    unsigned long long r;
    asm("mov.b64 %0, {%1, %2};" : "=l"(r) : "f"(lo), "f"(hi));
    return r;
}
__device__ __forceinline__ void upk2(unsigned long long v, float& lo, float& hi) {
    asm("mov.b64 {%0, %1}, %2;" : "=f"(lo), "=f"(hi) : "l"(v));
}
__device__ __forceinline__ unsigned long long fma2(unsigned long long a,
                                                   unsigned long long b,
                                                   unsigned long long c) {
    unsigned long long d;
    asm("fma.rn.f32x2 %0, %1, %2, %3;" : "=l"(d) : "l"(a), "l"(b), "l"(c));
    return d;
}
__device__ __forceinline__ unsigned long long mul2(unsigned long long a,
                                                   unsigned long long b) {
    unsigned long long d;
    asm("mul.rn.f32x2 %0, %1, %2;" : "=l"(d) : "l"(a), "l"(b));
    return d;
}

// alpha = atan(10*d)/pi + 0.5, minimax degree-11 odd poly, |err| < ~1e-6
__device__ __forceinline__ float fast_alpha(float d) {
    float z  = 10.0f * d;
    float az = fabsf(z);
    float r;
    asm("rcp.approx.f32 %0, %1;" : "=f"(r) : "f"(az));
    bool  big = az > 1.0f;
    float w   = big ? r : az;
    float u   = w * w;
    float q   = -0.003730699f;
    q = fmaf(q, u,  0.016758625f);
    q = fmaf(q, u, -0.037058160f);
    q = fmaf(q, u,  0.061602231f);
    q = fmaf(q, u, -0.105877602f);
    q = fmaf(q, u,  0.318303375f);   // atan(w)/pi
    q = q * w;
    bool  pos  = z >= 0.0f;
    float base = big ? (pos ? 1.0f : 0.0f) : 0.5f;
    float sq   = (pos != big) ? q : -q;
    return base + sq;
}

__global__ __launch_bounds__(TPB)
void diffsort_loss_kernel(const float* __restrict__ pred,
                          const float* __restrict__ labels,
                          const float* __restrict__ ema,
                          float* __restrict__ out)
{
    __shared__ float s_ema[8];
    if (threadIdx.x < 8) s_ema[threadIdx.x] = ema[threadIdx.x];
    __syncthreads();

    const int row = blockIdx.x * TPB + threadIdx.x;

    const float4* p4 = reinterpret_cast<const float4*>(pred   + (size_t)row * 8);
    const float4* l4 = reinterpret_cast<const float4*>(labels + (size_t)row * 8);
    float4 pa = p4[0], pb = p4[1];
    float4 la = l4[0], lb = l4[1];

    float pr[8]  = {pa.x, pa.y, pa.z, pa.w, pb.x, pb.y, pb.z, pb.w};
    float lab[8] = {la.x, la.y, la.z, la.w, lb.x, lb.y, lb.z, lb.w};

    // rank_true[i]: descending rank of labels[i], stable tie-break by index.
    // Triangular: pair (i<j): c = lab[j] > lab[i] -> rt[i]+=c, rt[j]+=1-c
    // (ties: c=false -> rt[j]+=1, matching "equal and j<i" rule).
    int rt[8] = {0, 0, 0, 0, 0, 0, 0, 0};
    #pragma unroll
    for (int i = 0; i < 8; i++) {
        #pragma unroll
        for (int j = i + 1; j < 8; j++) {
            int c = lab[j] > lab[i];
            rt[i] += c;
            rt[j] += 1 - c;
        }
    }

    // x = -(pred - rank_ema[rank_true])
    float x[8];
    #pragma unroll
    for (int i = 0; i < 8; i++) x[i] = s_ema[rt[i]] - pr[i];

    const unsigned long long ONE2 = pk2(1.0f, 1.0f);
    const unsigned long long NEG2 = pk2(-1.0f, -1.0f);

    // P packed as 4 row-pair packs x 8 cols; init identity
    unsigned long long P2[4][8];
    #pragma unroll
    for (int k = 0; k < 4; k++) {
        #pragma unroll
        for (int c = 0; c < 8; c++) {
            P2[k][c] = pk2((c == 2 * k) ? 1.0f : 0.0f,
                           (c == 2 * k + 1) ? 1.0f : 0.0f);
        }
    }

    // comparator on (i, i+1), touching only packs [PLO, PHI] (rows outside
    // these packs are provably zero in both columns at that point)
#define CPAIR(i, PLO, PHI) do {                                             \
        float a_ = x[i], b_ = x[(i) + 1];                                   \
        float al_ = fast_alpha(b_ - a_);                                    \
        float t_  = a_ - b_;                                                \
        x[i]       = fmaf(al_,  t_, b_);                                    \
        x[(i) + 1] = fmaf(-al_, t_, a_);                                    \
        unsigned long long al2_  = pk2(al_, al_);                           \
        unsigned long long nal2_ = pk2(-al_, -al_);                         \
        _Pragma("unroll")                                                   \
        for (int k_ = (PLO); k_ <= (PHI); k_++) {                           \
            unsigned long long A_ = P2[k_][i], B_ = P2[k_][(i) + 1];        \
            unsigned long long t2_ = fma2(B_, NEG2, A_);      /* A - B */   \
            P2[k_][i]       = fma2(al2_,  t2_, B_);                         \
            P2[k_][(i) + 1] = fma2(nal2_, t2_, A_);                         \
        }                                                                   \
    } while (0)

    // odd-even network, 8 layers, with per-comparator live pack ranges
    CPAIR(0,0,0); CPAIR(2,1,1); CPAIR(4,2,2); CPAIR(6,3,3);   // L0
    CPAIR(1,0,1); CPAIR(3,1,2); CPAIR(5,2,3);                 // L1
    CPAIR(0,0,1); CPAIR(2,0,2); CPAIR(4,1,3); CPAIR(6,2,3);   // L2
    CPAIR(1,0,2); CPAIR(3,0,3); CPAIR(5,1,3);                 // L3
    CPAIR(0,0,2); CPAIR(2,0,3); CPAIR(4,0,3); CPAIR(6,1,3);   // L4
    CPAIR(1,0,3); CPAIR(3,0,3); CPAIR(5,0,3);                 // L5
    CPAIR(0,0,3); CPAIR(2,0,3); CPAIR(4,0,3); CPAIR(6,0,3);   // L6
    CPAIR(1,0,3); CPAIR(3,0,3); CPAIR(5,0,3);                 // L7
#undef CPAIR

    // loss: sum_{ij} log1p(-p) + sum_i [log(p_g) - log1p(-p_g)], g=(i, rt[i])
    // column sum of log1p(-p) == log(prod_r (1-p_rc)); take cols in pairs.
    float s = 0.0f;
    float colprod[8];
    #pragma unroll
    for (int c = 0; c < 8; c++) {
        unsigned long long o0 = fma2(P2[0][c], NEG2, ONE2);
        unsigned long long o1 = fma2(P2[1][c], NEG2, ONE2);
        unsigned long long o2 = fma2(P2[2][c], NEG2, ONE2);
        unsigned long long o3 = fma2(P2[3][c], NEG2, ONE2);
        unsigned long long m  = mul2(mul2(o0, o1), mul2(o2, o3));
        float lo, hi;
        upk2(m, lo, hi);
        colprod[c] = lo * hi;
    }
    #pragma unroll
    for (int c = 0; c < 8; c += 2) s += __logf(colprod[c] * colprod[c + 1]);

    #pragma unroll
    for (int i = 0; i < 8; i++) {
        unsigned long long g2 = P2[i >> 1][0];
        #pragma unroll
        for (int j = 1; j < 8; j++) g2 = (rt[i] == j) ? P2[i >> 1][j] : g2;
        float glo, ghi;
        upk2(g2, glo, ghi);
        float pg = (i & 1) ? ghi : glo;
        s += fmaxf(__logf(pg), -100.0f) - __logf(1.0f - pg);
    }

    // deterministic block reduction
    #pragma unroll
    for (int o = 16; o > 0; o >>= 1) s += __shfl_xor_sync(0xffffffffu, s, o);
    __shared__ float ws[TPB / 32];
    __shared__ bool s_last;
    if ((threadIdx.x & 31) == 0) ws[threadIdx.x >> 5] = s;
    __syncthreads();
    if (threadIdx.x == 0) {
        float bs = 0.0f;
        #pragma unroll
        for (int w = 0; w < TPB / 32; w++) bs += ws[w];
        g_partials[blockIdx.x] = bs;
        __threadfence();
        unsigned int old = atomicAdd(&g_count, 1u);
        s_last = (old == NBLK - 1);
    }
    __syncthreads();

    // last block performs the (deterministic, fixed-order) final reduction
    if (s_last) {
        const int t = threadIdx.x;
        double ds = 0.0;
        #pragma unroll
        for (int k = 0; k < NBLK / TPB; k++)
            ds += (double)g_partials[t + k * TPB];
        #pragma unroll
        for (int o = 16; o > 0; o >>= 1) ds += __shfl_xor_sync(0xffffffffu, ds, o);
        __shared__ double wd[TPB / 32];
        if ((t & 31) == 0) wd[t >> 5] = ds;
        __syncthreads();
        if (t == 0) {
            double tot = 0.0;
            #pragma unroll
            for (int w = 0; w < TPB / 32; w++) tot += wd[w];
            out[0] = (float)(-tot / ((double)BATCH_N * 64.0));
            g_count = 0;   // reset for next graph replay
        }
    }
}

extern "C" void kernel_launch(void* const* d_in, const int* in_sizes, int n_in,
                              void* d_out, int out_size)
{
    const float* pred   = (const float*)d_in[0];
    const float* labels = (const float*)d_in[1];
    const float* ema    = (const float*)d_in[2];
    diffsort_loss_kernel<<<NBLK, TPB>>>(pred, labels, ema, (float*)d_out);
}

// round 4
// speedup vs baseline: 1.3938x; 1.3938x over previous
#include <cuda_runtime.h>

#define BATCH_N 262144
#define TPB     128
#define NBLK    (BATCH_N / TPB)   // 2048

__device__ float g_partials[NBLK];
__device__ unsigned int g_count = 0;

// alpha = atan(10*d)/pi + 0.5, minimax degree-11 odd poly, |err| < ~1e-6
__device__ __forceinline__ float fast_alpha(float d) {
    float z  = 10.0f * d;
    float az = fabsf(z);
    float r;
    asm("rcp.approx.f32 %0, %1;" : "=f"(r) : "f"(az));
    bool  big = az > 1.0f;
    float w   = big ? r : az;
    float u   = w * w;
    float q   = -0.003730699f;
    q = fmaf(q, u,  0.016758625f);
    q = fmaf(q, u, -0.037058160f);
    q = fmaf(q, u,  0.061602231f);
    q = fmaf(q, u, -0.105877602f);
    q = fmaf(q, u,  0.318303375f);   // atan(w)/pi
    q = q * w;
    bool  pos  = z >= 0.0f;
    float base = big ? (pos ? 1.0f : 0.0f) : 0.5f;
    float sq   = (pos != big) ? q : -q;
    return base + sq;
}

__global__ __launch_bounds__(TPB, 4)
void diffsort_loss_kernel(const float* __restrict__ pred,
                          const float* __restrict__ labels,
                          const float* __restrict__ ema,
                          float* __restrict__ out)
{
    __shared__ float s_ema[8];
    if (threadIdx.x < 8) s_ema[threadIdx.x] = ema[threadIdx.x];
    __syncthreads();

    const int row = blockIdx.x * TPB + threadIdx.x;

    const float4* p4 = reinterpret_cast<const float4*>(pred   + (size_t)row * 8);
    const float4* l4 = reinterpret_cast<const float4*>(labels + (size_t)row * 8);
    float4 pa = p4[0], pb = p4[1];
    float4 la = l4[0], lb = l4[1];

    float pr[8]  = {pa.x, pa.y, pa.z, pa.w, pb.x, pb.y, pb.z, pb.w};
    float lab[8] = {la.x, la.y, la.z, la.w, lb.x, lb.y, lb.z, lb.w};

    // rank_true[i]: descending rank of labels[i], stable tie-break by index.
    // Triangular: pair (i<j): c = lab[j] > lab[i] -> rt[i]+=c, rt[j]+=1-c
    int rt[8] = {0, 0, 0, 0, 0, 0, 0, 0};
    #pragma unroll
    for (int i = 0; i < 8; i++) {
        #pragma unroll
        for (int j = i + 1; j < 8; j++) {
            int c = lab[j] > lab[i];
            rt[i] += c;
            rt[j] += 1 - c;
        }
    }

    // x = -(pred - rank_ema[rank_true])
    float x[8];
    #pragma unroll
    for (int i = 0; i < 8; i++) x[i] = s_ema[rt[i]] - pr[i];

    // P in registers, identity
    float P[8][8];
    #pragma unroll
    for (int r = 0; r < 8; r++) {
        #pragma unroll
        for (int c = 0; c < 8; c++) P[r][c] = (r == c) ? 1.0f : 0.0f;
    }

    // comparator on wires (i, i+1); only rows [RLO, RHI] can be nonzero in
    // columns i, i+1 at this point (verified by support-set propagation).
    // UPX=0 skips the dead x-update (final layer).
#define CPAIR(i, RLO, RHI, UPX) do {                                        \
        float a_ = x[i], b_ = x[(i) + 1];                                   \
        float al_ = fast_alpha(b_ - a_);                                    \
        if (UPX) {                                                          \
            float t_ = a_ - b_;                                             \
            x[i]       = fmaf(al_,  t_, b_);                                \
            x[(i) + 1] = fmaf(-al_, t_, a_);                                \
        }                                                                   \
        _Pragma("unroll")                                                   \
        for (int r_ = (RLO); r_ <= (RHI); r_++) {                           \
            float A_ = P[r_][i], B_ = P[r_][(i) + 1];                       \
            float t2_ = A_ - B_;                                            \
            P[r_][i]       = fmaf(al_,  t2_, B_);                           \
            P[r_][(i) + 1] = fmaf(-al_, t2_, A_);                           \
        }                                                                   \
    } while (0)

    CPAIR(0,0,1,1); CPAIR(2,2,3,1); CPAIR(4,4,5,1); CPAIR(6,6,7,1);  // L0
    CPAIR(1,0,3,1); CPAIR(3,2,5,1); CPAIR(5,4,7,1);                  // L1
    CPAIR(0,0,3,1); CPAIR(2,0,5,1); CPAIR(4,2,7,1); CPAIR(6,4,7,1);  // L2
    CPAIR(1,0,5,1); CPAIR(3,0,7,1); CPAIR(5,2,7,1);                  // L3
    CPAIR(0,0,5,1); CPAIR(2,0,7,1); CPAIR(4,0,7,1); CPAIR(6,2,7,1);  // L4
    CPAIR(1,0,7,1); CPAIR(3,0,7,1); CPAIR(5,0,7,1);                  // L5
    CPAIR(0,0,7,1); CPAIR(2,0,7,1); CPAIR(4,0,7,1); CPAIR(6,0,7,1);  // L6
    CPAIR(1,0,7,0); CPAIR(3,0,7,0); CPAIR(5,0,7,0);                  // L7
#undef CPAIR

    // loss = sum_{ij} log1p(-p) + sum_i [log(p_g) - log1p(-p_g)], g=(i,rt[i])
    // column sum of log1p(-p) == log(prod_r (1-p_rc)); prod via fused
    // prod*(1-p) = fmaf(-prod, p, prod). Columns paired into one log each.
    float s = 0.0f;
    #pragma unroll
    for (int c = 0; c < 8; c += 2) {
        float pe = 1.0f, po = 1.0f;
        #pragma unroll
        for (int r = 0; r < 8; r++) {
            pe = fmaf(-pe, P[r][c],     pe);
            po = fmaf(-po, P[r][c + 1], po);
        }
        s += __logf(pe * po);
    }

    #pragma unroll
    for (int i = 0; i < 8; i++) {
        // 3-level bit-select tree for pg = P[i][rt[i]]
        int  ri = rt[i];
        bool b0 = ri & 1, b1 = ri & 2, b2 = ri & 4;
        float s0 = b0 ? P[i][1] : P[i][0];
        float s1 = b0 ? P[i][3] : P[i][2];
        float s2 = b0 ? P[i][5] : P[i][4];
        float s3 = b0 ? P[i][7] : P[i][6];
        float t0 = b1 ? s1 : s0;
        float t1 = b1 ? s3 : s2;
        float pg = b2 ? t1 : t0;
        s += fmaxf(__logf(pg), -100.0f) - __logf(1.0f - pg);
    }

    // deterministic block reduction
    #pragma unroll
    for (int o = 16; o > 0; o >>= 1) s += __shfl_xor_sync(0xffffffffu, s, o);
    __shared__ float ws[TPB / 32];
    __shared__ bool s_last;
    if ((threadIdx.x & 31) == 0) ws[threadIdx.x >> 5] = s;
    __syncthreads();
    if (threadIdx.x == 0) {
        float bs = 0.0f;
        #pragma unroll
        for (int w = 0; w < TPB / 32; w++) bs += ws[w];
        g_partials[blockIdx.x] = bs;
        __threadfence();
        unsigned int old = atomicAdd(&g_count, 1u);
        s_last = (old == NBLK - 1);
    }
    __syncthreads();

    // last block performs the deterministic, fixed-order final reduction
    if (s_last) {
        const int t = threadIdx.x;
        double ds = 0.0;
        #pragma unroll
        for (int k = 0; k < NBLK / TPB; k++)
            ds += (double)g_partials[t + k * TPB];
        #pragma unroll
        for (int o = 16; o > 0; o >>= 1) ds += __shfl_xor_sync(0xffffffffu, ds, o);
        __shared__ double wd[TPB / 32];
        if ((t & 31) == 0) wd[t >> 5] = ds;
        __syncthreads();
        if (t == 0) {
            double tot = 0.0;
            #pragma unroll
            for (int w = 0; w < TPB / 32; w++) tot += wd[w];
            out[0] = (float)(-tot / ((double)BATCH_N * 64.0));
            g_count = 0;   // reset for next graph replay
        }
    }
}

extern "C" void kernel_launch(void* const* d_in, const int* in_sizes, int n_in,
                              void* d_out, int out_size)
{
    const float* pred   = (const float*)d_in[0];
    const float* labels = (const float*)d_in[1];
    const float* ema    = (const float*)d_in[2];
    diffsort_loss_kernel<<<NBLK, TPB>>>(pred, labels, ema, (float*)d_out);
}

// round 5
// speedup vs baseline: 1.5023x; 1.0779x over previous
#include <cuda_runtime.h>

#define BATCH_N 262144
#define TPB     128
#define NBLK    (BATCH_N / TPB)   // 2048

__device__ float g_partials[NBLK];
__device__ unsigned int g_count = 0;

// alpha = atan(10*d)/pi + 0.5, minimax degree-11 odd poly, |err| < ~1e-6.
// Signed-w form: w = (|z|>1) ? 1/z : z (signed), q(w) odd => carries sign;
// alpha = base + s*q with s=-1 in the big branch (atan(z) = sgn*pi/2 - atan(1/z)).
__device__ __forceinline__ float fast_alpha(float d) {
    float z = 10.0f * d;
    float r;
    asm("rcp.approx.f32 %0, %1;" : "=f"(r) : "f"(z));
    bool  big = fabsf(z) > 1.0f;
    float w   = big ? r : z;
    float u   = w * w;
    float q   = -0.003730699f;
    q = fmaf(q, u,  0.016758625f);
    q = fmaf(q, u, -0.037058160f);
    q = fmaf(q, u,  0.061602231f);
    q = fmaf(q, u, -0.105877602f);
    q = fmaf(q, u,  0.318303375f);   // atan(w)/(pi*w)
    q = q * w;                       // atan(w)/pi, signed
    float base = big ? ((z > 0.0f) ? 1.0f : 0.0f) : 0.5f;
    float s    = big ? -1.0f : 1.0f;
    return fmaf(s, q, base);
}

__global__ __launch_bounds__(TPB, 5)
void diffsort_loss_kernel(const float* __restrict__ pred,
                          const float* __restrict__ labels,
                          const float* __restrict__ ema,
                          float* __restrict__ out)
{
    __shared__ float s_ema[8];
    if (threadIdx.x < 8) s_ema[threadIdx.x] = ema[threadIdx.x];
    __syncthreads();

    const int row = blockIdx.x * TPB + threadIdx.x;

    const float4* p4 = reinterpret_cast<const float4*>(pred   + (size_t)row * 8);
    const float4* l4 = reinterpret_cast<const float4*>(labels + (size_t)row * 8);
    float4 pa = p4[0], pb = p4[1];
    float4 la = l4[0], lb = l4[1];

    float pr[8]  = {pa.x, pa.y, pa.z, pa.w, pb.x, pb.y, pb.z, pb.w};
    float lab[8] = {la.x, la.y, la.z, la.w, lb.x, lb.y, lb.z, lb.w};

    // rank_true[i]: descending rank of labels[i], stable tie-break by index.
    int rt[8] = {0, 0, 0, 0, 0, 0, 0, 0};
    #pragma unroll
    for (int i = 0; i < 8; i++) {
        #pragma unroll
        for (int j = i + 1; j < 8; j++) {
            int c = lab[j] > lab[i];
            rt[i] += c;
            rt[j] += 1 - c;
        }
    }

    // x = -(pred - rank_ema[rank_true])
    float x[8];
    #pragma unroll
    for (int i = 0; i < 8; i++) x[i] = s_ema[rt[i]] - pr[i];

    // P in registers, identity
    float P[8][8];
    #pragma unroll
    for (int r = 0; r < 8; r++) {
        #pragma unroll
        for (int c = 0; c < 8; c++) P[r][c] = (r == c) ? 1.0f : 0.0f;
    }

    // comparator on wires (i, i+1); only rows [RLO, RHI] can be nonzero in
    // columns i, i+1 at this point (support-set propagation). UPX=0 skips
    // the dead x-update on the final layer.
#define CPAIR(i, RLO, RHI, UPX) do {                                        \
        float a_ = x[i], b_ = x[(i) + 1];                                   \
        float al_ = fast_alpha(b_ - a_);                                    \
        if (UPX) {                                                          \
            float t_ = a_ - b_;                                             \
            x[i]       = fmaf(al_,  t_, b_);                                \
            x[(i) + 1] = fmaf(-al_, t_, a_);                                \
        }                                                                   \
        _Pragma("unroll")                                                   \
        for (int r_ = (RLO); r_ <= (RHI); r_++) {                           \
            float A_ = P[r_][i], B_ = P[r_][(i) + 1];                       \
            float t2_ = A_ - B_;                                            \
            P[r_][i]       = fmaf(al_,  t2_, B_);                           \
            P[r_][(i) + 1] = fmaf(-al_, t2_, A_);                           \
        }                                                                   \
    } while (0)

    CPAIR(0,0,1,1); CPAIR(2,2,3,1); CPAIR(4,4,5,1); CPAIR(6,6,7,1);  // L0
    CPAIR(1,0,3,1); CPAIR(3,2,5,1); CPAIR(5,4,7,1);                  // L1
    CPAIR(0,0,3,1); CPAIR(2,0,5,1); CPAIR(4,2,7,1); CPAIR(6,4,7,1);  // L2
    CPAIR(1,0,5,1); CPAIR(3,0,7,1); CPAIR(5,2,7,1);                  // L3
    CPAIR(0,0,5,1); CPAIR(2,0,7,1); CPAIR(4,0,7,1); CPAIR(6,2,7,1);  // L4
    CPAIR(1,0,7,1); CPAIR(3,0,7,1); CPAIR(5,0,7,1);                  // L5
    CPAIR(0,0,7,1); CPAIR(2,0,7,1); CPAIR(4,0,7,1); CPAIR(6,0,7,1);  // L6
    CPAIR(1,0,7,0); CPAIR(3,0,7,0); CPAIR(5,0,7,0);                  // L7
#undef CPAIR

    // loss = sum_{ij} log1p(-p) + sum_i [log(p_g) - log1p(-p_g)], g=(i,rt[i]).
    // All logs accumulated in log2 units; ln2 folded into the final scale.
    // -100 clip provably never fires: min P entry >= (1/(pi*10*|d|max))^7 ~ 6e-18.
    float s = 0.0f;
    #pragma unroll
    for (int c = 0; c < 8; c += 2) {
        float pe = 1.0f, po = 1.0f;
        #pragma unroll
        for (int r = 0; r < 8; r++) {
            pe = fmaf(-pe, P[r][c],     pe);   // pe *= (1 - P[r][c])
            po = fmaf(-po, P[r][c + 1], po);
        }
        s += __log2f(pe * po);
    }

    #pragma unroll
    for (int i = 0; i < 8; i++) {
        // 3-level bit-select tree for pg = P[i][rt[i]]
        int  ri = rt[i];
        bool b0 = ri & 1, b1 = ri & 2, b2 = ri & 4;
        float s0 = b0 ? P[i][1] : P[i][0];
        float s1 = b0 ? P[i][3] : P[i][2];
        float s2 = b0 ? P[i][5] : P[i][4];
        float s3 = b0 ? P[i][7] : P[i][6];
        float t0 = b1 ? s1 : s0;
        float t1 = b1 ? s3 : s2;
        float pg = b2 ? t1 : t0;
        s += __log2f(pg) - __log2f(1.0f - pg);
    }

    // deterministic block reduction
    #pragma unroll
    for (int o = 16; o > 0; o >>= 1) s += __shfl_xor_sync(0xffffffffu, s, o);
    __shared__ float ws[TPB / 32];
    __shared__ bool s_last;
    if ((threadIdx.x & 31) == 0) ws[threadIdx.x >> 5] = s;
    __syncthreads();
    if (threadIdx.x == 0) {
        float bs = 0.0f;
        #pragma unroll
        for (int w = 0; w < TPB / 32; w++) bs += ws[w];
        g_partials[blockIdx.x] = bs;
        __threadfence();
        unsigned int old = atomicAdd(&g_count, 1u);
        s_last = (old == NBLK - 1);
    }
    __syncthreads();

    // last block performs the deterministic, fixed-order final reduction
    if (s_last) {
        const int t = threadIdx.x;
        double ds = 0.0;
        #pragma unroll
        for (int k = 0; k < NBLK / TPB; k++)
            ds += (double)g_partials[t + k * TPB];
        #pragma unroll
        for (int o = 16; o > 0; o >>= 1) ds += __shfl_xor_sync(0xffffffffu, ds, o);
        __shared__ double wd[TPB / 32];
        if ((t & 31) == 0) wd[t >> 5] = ds;
        __syncthreads();
        if (t == 0) {
            double tot = 0.0;
            #pragma unroll
            for (int w = 0; w < TPB / 32; w++) tot += wd[w];
            // tot is in log2 units: loss = -ln2 * tot / (B*64)
            out[0] = (float)(-tot * 0.6931471805599453
                             / ((double)BATCH_N * 64.0));
            g_count = 0;   // reset for next graph replay
        }
    }
}

extern "C" void kernel_launch(void* const* d_in, const int* in_sizes, int n_in,
                              void* d_out, int out_size)
{
    const float* pred   = (const float*)d_in[0];
    const float* labels = (const float*)d_in[1];
    const float* ema    = (const float*)d_in[2];
    diffsort_loss_kernel<<<NBLK, TPB>>>(pred, labels, ema, (float*)d_out);
}